// round 1
// baseline (speedup 1.0000x reference)
#include <cuda_runtime.h>
#include <math.h>
#include <float.h>

#define B_ 4096
#define D_ 1024
#define C_ 11003
#define SCALE_ 28.0f
#define EPS_LS_ 0.1f
#define T_ 4.0f
#define SPOS_ 10.0f
#define SNEG_ 40.0f
#define ALPHA_ 0.6f
#define BETA_ 0.4f
#define HDR_A_ 3.0f
#define PLEN_ 63
#define LOG_1EM12 -27.631021115928547f

// ---------------- scratch (static device memory; no allocations) ----------------
__device__ float g_vn[B_ * D_];
__device__ float g_tn[B_ * D_];
__device__ float g_sqv[B_];
__device__ float g_sqt[B_];
__device__ float g_invW[C_];
__device__ float g_invWt[C_];
__device__ float g_logA[(size_t)B_ * C_];   // visual logits, later reused for filter logits
__device__ float g_logB[(size_t)B_ * C_];   // textual logits
__device__ float g_Gv[(size_t)B_ * B_];
__device__ float g_Gt[(size_t)B_ * B_];
__device__ float g_Gs[(size_t)B_ * B_];
// accumulators: 0=CE_v 1=CE_t 2=CE_filter 3=dist_f 4=KL 5=HDR 6=GA
__device__ double g_acc[8];

// ---------------- kernels ----------------

__global__ void zero_acc_kernel() {
    if (threadIdx.x < 8) g_acc[threadIdx.x] = 0.0;
}

// Row-normalize both embeddings; also accumulate dist_f = sum ||vn - tn||^2 and
// exact squared norms of the normalized rows (for pdist).
__global__ void normalize_kernel(const float* __restrict__ V, const float* __restrict__ Tm) {
    const int row = blockIdx.x;
    const int tid = threadIdx.x;
    const float* v = V + (size_t)row * D_;
    const float* t = Tm + (size_t)row * D_;

    float vv[4], tt[4];
    float lv = 0.f, lt = 0.f;
#pragma unroll
    for (int i = 0; i < 4; i++) {
        vv[i] = v[tid + 256 * i];
        tt[i] = t[tid + 256 * i];
        lv += vv[i] * vv[i];
        lt += tt[i] * tt[i];
    }
    __shared__ float s1[256], s2[256];
    s1[tid] = lv; s2[tid] = lt;
    __syncthreads();
    for (int s = 128; s > 0; s >>= 1) {
        if (tid < s) { s1[tid] += s1[tid + s]; s2[tid] += s2[tid + s]; }
        __syncthreads();
    }
    const float sumv = s1[0], sumt = s2[0];
    __syncthreads();
    const float invv = 1.0f / sqrtf(sumv);
    const float invt = 1.0f / sqrtf(sumt);

    float ld = 0.f;
#pragma unroll
    for (int i = 0; i < 4; i++) {
        float a = vv[i] * invv;
        float b = tt[i] * invt;
        g_vn[(size_t)row * D_ + tid + 256 * i] = a;
        g_tn[(size_t)row * D_ + tid + 256 * i] = b;
        float df = a - b;
        ld += df * df;
    }
    s1[tid] = ld;
    __syncthreads();
    for (int s = 128; s > 0; s >>= 1) {
        if (tid < s) s1[tid] += s1[tid + s];
        __syncthreads();
    }
    if (tid == 0) {
        atomicAdd(&g_acc[3], (double)s1[0]);
        g_sqv[row] = sumv * invv * invv;
        g_sqt[row] = sumt * invt * invt;
    }
}

// Per-column inverse norms of W and W_text (column-major access is coalesced:
// adjacent threads -> adjacent columns).
__global__ void colnorm_kernel(const float* __restrict__ W, const float* __restrict__ Wt) {
    int c = blockIdx.x * blockDim.x + threadIdx.x;
    if (c >= C_) return;
    float s1 = 0.f, s2 = 0.f;
    for (int d = 0; d < D_; d++) {
        float a = W[(size_t)d * C_ + c];
        float b = Wt[(size_t)d * C_ + c];
        s1 += a * a;
        s2 += b * b;
    }
    g_invW[c] = 1.0f / sqrtf(s1);
    g_invWt[c] = 1.0f / sqrtf(s2);
}

// Out[b,c] = SCALE * inv[c] * sum_d A[b,d]*Wm[d,c].  A:[M,K] rm, Wm:[K,N] rm.
// 128x128x8 tile, 256 threads, 8x8 per thread.
__global__ void __launch_bounds__(256) gemm_nn_kernel(
    const float* __restrict__ A, const float* __restrict__ Wm,
    const float* __restrict__ inv, float* __restrict__ Out,
    int M, int N, int K) {
    __shared__ float As[8][128];
    __shared__ float Bs[8][128];
    const int tid = threadIdx.x;
    const int tx = tid & 15, ty = tid >> 4;
    const int rowBase = blockIdx.y * 128, colBase = blockIdx.x * 128;
    const int a_r = tid >> 1, a_k = (tid & 1) * 4;
    const int b_r = tid >> 5, b_c = (tid & 31) * 4;

    float acc[8][8];
#pragma unroll
    for (int i = 0; i < 8; i++)
#pragma unroll
        for (int j = 0; j < 8; j++) acc[i][j] = 0.f;

    for (int kt = 0; kt < K; kt += 8) {
        float4 av = *reinterpret_cast<const float4*>(&A[(size_t)(rowBase + a_r) * K + kt + a_k]);
        As[a_k + 0][a_r] = av.x;
        As[a_k + 1][a_r] = av.y;
        As[a_k + 2][a_r] = av.z;
        As[a_k + 3][a_r] = av.w;
#pragma unroll
        for (int l = 0; l < 4; l++) {
            int gc = colBase + b_c + l;
            Bs[b_r][b_c + l] = (gc < N) ? Wm[(size_t)(kt + b_r) * N + gc] : 0.f;
        }
        __syncthreads();
#pragma unroll
        for (int k = 0; k < 8; k++) {
            float4 ra0 = *reinterpret_cast<const float4*>(&As[k][ty * 8]);
            float4 ra1 = *reinterpret_cast<const float4*>(&As[k][ty * 8 + 4]);
            float4 rb0 = *reinterpret_cast<const float4*>(&Bs[k][tx * 8]);
            float4 rb1 = *reinterpret_cast<const float4*>(&Bs[k][tx * 8 + 4]);
            float ra[8] = {ra0.x, ra0.y, ra0.z, ra0.w, ra1.x, ra1.y, ra1.z, ra1.w};
            float rb[8] = {rb0.x, rb0.y, rb0.z, rb0.w, rb1.x, rb1.y, rb1.z, rb1.w};
#pragma unroll
            for (int i = 0; i < 8; i++)
#pragma unroll
                for (int j = 0; j < 8; j++) acc[i][j] += ra[i] * rb[j];
        }
        __syncthreads();
    }
#pragma unroll
    for (int i = 0; i < 8; i++) {
        int r = rowBase + ty * 8 + i;
#pragma unroll
        for (int j = 0; j < 8; j++) {
            int cidx = colBase + tx * 8 + j;
            if (cidx < N) Out[(size_t)r * N + cidx] = acc[i][j] * (SCALE_ * inv[cidx]);
        }
    }
}

// Out[i,j] = sum_d A[i,d]*Bm[j,d].  A:[M,K] rm, Bm:[N,K] rm. M=N=4096, no guards.
__global__ void __launch_bounds__(256) gemm_nt_kernel(
    const float* __restrict__ A, const float* __restrict__ Bm, float* __restrict__ Out,
    int M, int N, int K) {
    __shared__ float As[8][128];
    __shared__ float Bs[8][128];
    const int tid = threadIdx.x;
    const int tx = tid & 15, ty = tid >> 4;
    const int rowBase = blockIdx.y * 128, colBase = blockIdx.x * 128;
    const int a_r = tid >> 1, a_k = (tid & 1) * 4;

    float acc[8][8];
#pragma unroll
    for (int i = 0; i < 8; i++)
#pragma unroll
        for (int j = 0; j < 8; j++) acc[i][j] = 0.f;

    for (int kt = 0; kt < K; kt += 8) {
        float4 av = *reinterpret_cast<const float4*>(&A[(size_t)(rowBase + a_r) * K + kt + a_k]);
        As[a_k + 0][a_r] = av.x;
        As[a_k + 1][a_r] = av.y;
        As[a_k + 2][a_r] = av.z;
        As[a_k + 3][a_r] = av.w;
        float4 bv = *reinterpret_cast<const float4*>(&Bm[(size_t)(colBase + a_r) * K + kt + a_k]);
        Bs[a_k + 0][a_r] = bv.x;
        Bs[a_k + 1][a_r] = bv.y;
        Bs[a_k + 2][a_r] = bv.z;
        Bs[a_k + 3][a_r] = bv.w;
        __syncthreads();
#pragma unroll
        for (int k = 0; k < 8; k++) {
            float4 ra0 = *reinterpret_cast<const float4*>(&As[k][ty * 8]);
            float4 ra1 = *reinterpret_cast<const float4*>(&As[k][ty * 8 + 4]);
            float4 rb0 = *reinterpret_cast<const float4*>(&Bs[k][tx * 8]);
            float4 rb1 = *reinterpret_cast<const float4*>(&Bs[k][tx * 8 + 4]);
            float ra[8] = {ra0.x, ra0.y, ra0.z, ra0.w, ra1.x, ra1.y, ra1.z, ra1.w};
            float rb[8] = {rb0.x, rb0.y, rb0.z, rb0.w, rb1.x, rb1.y, rb1.z, rb1.w};
#pragma unroll
            for (int i = 0; i < 8; i++)
#pragma unroll
                for (int j = 0; j < 8; j++) acc[i][j] += ra[i] * rb[j];
        }
        __syncthreads();
    }
#pragma unroll
    for (int i = 0; i < 8; i++) {
        int r = rowBase + ty * 8 + i;
#pragma unroll
        for (int j = 0; j < 8; j++) {
            Out[(size_t)r * N + colBase + tx * 8 + j] = acc[i][j];
        }
    }
}

// Label-smoothed CE per row; accumulate into g_acc[accIdx].
__global__ void ce_kernel(const float* __restrict__ logits, const int* __restrict__ labels,
                          int accIdx) {
    const int row = blockIdx.x;
    const int tid = threadIdx.x;
    const float* x = logits + (size_t)row * C_;
    __shared__ float s1[256], s2[256];

    float mx = -FLT_MAX;
    for (int c = tid; c < C_; c += 256) mx = fmaxf(mx, x[c]);
    s1[tid] = mx;
    __syncthreads();
    for (int s = 128; s > 0; s >>= 1) {
        if (tid < s) s1[tid] = fmaxf(s1[tid], s1[tid + s]);
        __syncthreads();
    }
    mx = s1[0];
    __syncthreads();

    float se = 0.f, sx = 0.f;
    for (int c = tid; c < C_; c += 256) {
        float v = x[c];
        se += expf(v - mx);
        sx += v;
    }
    s1[tid] = se; s2[tid] = sx;
    __syncthreads();
    for (int s = 128; s > 0; s >>= 1) {
        if (tid < s) { s1[tid] += s1[tid + s]; s2[tid] += s2[tid + s]; }
        __syncthreads();
    }
    if (tid == 0) {
        float lse = mx + logf(s1[0]);
        float picked = x[labels[row]];
        double ce = -((1.0 - (double)EPS_LS_) * ((double)picked - lse) +
                      ((double)EPS_LS_ / C_) * ((double)s2[0] - (double)C_ * lse));
        atomicAdd(&g_acc[accIdx], ce);
    }
}

// KL(teacher=visual logits xt, student=textual logits xs) at temperature T.
__global__ void kl_kernel(const float* __restrict__ teach, const float* __restrict__ stud) {
    const int row = blockIdx.x;
    const int tid = threadIdx.x;
    const float* xt = teach + (size_t)row * C_;
    const float* xs = stud + (size_t)row * C_;
    __shared__ float s1[256], s2[256];

    float mt = -FLT_MAX, ms = -FLT_MAX;
    for (int c = tid; c < C_; c += 256) {
        mt = fmaxf(mt, xt[c]);
        ms = fmaxf(ms, xs[c]);
    }
    s1[tid] = mt; s2[tid] = ms;
    __syncthreads();
    for (int s = 128; s > 0; s >>= 1) {
        if (tid < s) {
            s1[tid] = fmaxf(s1[tid], s1[tid + s]);
            s2[tid] = fmaxf(s2[tid], s2[tid + s]);
        }
        __syncthreads();
    }
    mt = s1[0]; ms = s2[0];
    __syncthreads();

    float set = 0.f, ses = 0.f;
    for (int c = tid; c < C_; c += 256) {
        set += expf((xt[c] - mt) / T_);
        ses += expf((xs[c] - ms) / T_);
    }
    s1[tid] = set; s2[tid] = ses;
    __syncthreads();
    for (int s = 128; s > 0; s >>= 1) {
        if (tid < s) { s1[tid] += s1[tid + s]; s2[tid] += s2[tid + s]; }
        __syncthreads();
    }
    const float lse_t = mt / T_ + logf(s1[0]);
    const float lse_s = ms / T_ + logf(s2[0]);
    __syncthreads();

    float acc = 0.f;
    for (int c = tid; c < C_; c += 256) {
        float lt = xt[c] / T_ - lse_t;
        float ls = xs[c] / T_ - lse_s;
        float tprob = expf(lt);
        float ltc = fmaxf(lt, LOG_1EM12);
        float lsc = fmaxf(ls, LOG_1EM12);
        acc += tprob * (ltc - lsc);
    }
    s1[tid] = acc;
    __syncthreads();
    for (int s = 128; s > 0; s >>= 1) {
        if (tid < s) s1[tid] += s1[tid + s];
        __syncthreads();
    }
    if (tid == 0) atomicAdd(&g_acc[4], (double)s1[0]);
}

// HardDarkRank: per row, top-63 teacher neighbors (excl self, tie -> smaller idx),
// then listwise -sum(ordered - suffix_lse) over the student scores.
__global__ void hdr_kernel() {
    const int row = blockIdx.x;
    const int tid = threadIdx.x;
    __shared__ float score[B_];
    __shared__ float sv[256];
    __shared__ int si[256];
    __shared__ int idxs[PLEN_];
    __shared__ float ord[PLEN_];

    const float sq_r = g_sqv[row];
    for (int j = tid; j < B_; j += 256) {
        float g = g_Gv[(size_t)row * B_ + j];
        float d2 = fmaxf(sq_r + g_sqv[j] - 2.0f * g, 1e-12f);
        float d = sqrtf(d2);
        score[j] = (j == row) ? -FLT_MAX : (-HDR_A_ * d * d * d);
    }
    __syncthreads();

    for (int k = 0; k < PLEN_; k++) {
        float best = -FLT_MAX;
        int bidx = 0x7fffffff;
        for (int j = tid; j < B_; j += 256) {
            float v = score[j];
            if (v > best || (v == best && j < bidx)) { best = v; bidx = j; }
        }
        sv[tid] = best; si[tid] = bidx;
        __syncthreads();
        for (int s = 128; s > 0; s >>= 1) {
            if (tid < s) {
                float ov = sv[tid + s]; int oi = si[tid + s];
                if (ov > sv[tid] || (ov == sv[tid] && oi < si[tid])) { sv[tid] = ov; si[tid] = oi; }
            }
            __syncthreads();
        }
        if (tid == 0) {
            idxs[k] = si[0];
            score[si[0]] = -FLT_MAX;
        }
        __syncthreads();
    }

    const float sqt_r = g_sqt[row];
    if (tid < PLEN_) {
        int j = idxs[tid];
        float g = g_Gt[(size_t)row * B_ + j];
        float d2 = fmaxf(sqt_r + g_sqt[j] - 2.0f * g, 1e-12f);
        float d = sqrtf(d2);
        ord[tid] = -HDR_A_ * d * d * d;
    }
    __syncthreads();
    if (tid == 0) {
        // reversed cumulative logsumexp; sum of (ordered - lse_tail)
        float acc = -FLT_MAX;
        float total = 0.f;
        for (int k = PLEN_ - 1; k >= 0; k--) {
            float o = ord[k];
            if (acc == -FLT_MAX) acc = o;
            else {
                float mx = fmaxf(acc, o);
                acc = mx + log1pf(expf(fminf(acc, o) - mx));
            }
            total += o - acc;
        }
        atomicAdd(&g_acc[5], (double)(-total));
    }
}

// Global align loss over sim = vn @ tn^T.
__global__ void galign_kernel(const int* __restrict__ labels) {
    const int tid = threadIdx.x;
    const size_t stride = (size_t)gridDim.x * blockDim.x;
    double local = 0.0;
    for (size_t e = (size_t)blockIdx.x * blockDim.x + tid; e < (size_t)B_ * B_; e += stride) {
        int i = (int)(e >> 12);   // /4096
        int j = (int)(e & 4095);
        float sim = g_Gs[e];
        bool same = labels[i] == labels[j];
        float x = same ? (-SPOS_ * (sim - ALPHA_)) : (SNEG_ * (sim - BETA_));
        local += (double)log1pf(expf(x));
    }
    __shared__ double sd[256];
    sd[tid] = local;
    __syncthreads();
    for (int s = 128; s > 0; s >>= 1) {
        if (tid < s) sd[tid] += sd[tid + s];
        __syncthreads();
    }
    if (tid == 0) atomicAdd(&g_acc[6], sd[0]);
}

__global__ void finalize_kernel(float* out) {
    const double invB = 1.0 / (double)B_;
    double v = (g_acc[0] + g_acc[1] + g_acc[2]) * invB   // 3x CE (L4=1)
             + g_acc[3] * invB                            // dist_f (L2=1)
             + g_acc[4] * invB                            // KL (L3=1)
             + 0.1 * g_acc[5] * invB                      // HDR
             + 2.0 * g_acc[6] * invB;                     // global align
    out[0] = (float)v;
}

// ---------------- launch ----------------
extern "C" void kernel_launch(void* const* d_in, const int* in_sizes, int n_in,
                              void* d_out, int out_size) {
    const float* V = (const float*)d_in[0];
    const float* Tx = (const float*)d_in[1];
    const int* labels = (const int*)d_in[2];
    const float* W = (const float*)d_in[3];
    const float* Wt = (const float*)d_in[4];
    float* out = (float*)d_out;

    float *vn, *tn, *invW, *invWt, *logA, *logB, *Gv, *Gt, *Gs;
    cudaGetSymbolAddress((void**)&vn, g_vn);
    cudaGetSymbolAddress((void**)&tn, g_tn);
    cudaGetSymbolAddress((void**)&invW, g_invW);
    cudaGetSymbolAddress((void**)&invWt, g_invWt);
    cudaGetSymbolAddress((void**)&logA, g_logA);
    cudaGetSymbolAddress((void**)&logB, g_logB);
    cudaGetSymbolAddress((void**)&Gv, g_Gv);
    cudaGetSymbolAddress((void**)&Gt, g_Gt);
    cudaGetSymbolAddress((void**)&Gs, g_Gs);

    zero_acc_kernel<<<1, 32>>>();
    normalize_kernel<<<B_, 256>>>(V, Tx);
    colnorm_kernel<<<(C_ + 255) / 256, 256>>>(W, Wt);

    dim3 gnn((C_ + 127) / 128, B_ / 128);
    gemm_nn_kernel<<<gnn, 256>>>(vn, W, invW, logA, B_, C_, D_);   // visual logits
    gemm_nn_kernel<<<gnn, 256>>>(tn, W, invW, logB, B_, C_, D_);   // textual logits
    ce_kernel<<<B_, 256>>>(logA, labels, 0);
    ce_kernel<<<B_, 256>>>(logB, labels, 1);
    kl_kernel<<<B_, 256>>>(logA, logB);
    gemm_nn_kernel<<<gnn, 256>>>(tn, Wt, invWt, logA, B_, C_, D_); // filter logits (reuse)
    ce_kernel<<<B_, 256>>>(logA, labels, 2);

    dim3 gnt(B_ / 128, B_ / 128);
    gemm_nt_kernel<<<gnt, 256>>>(vn, vn, Gv, B_, B_, D_);
    gemm_nt_kernel<<<gnt, 256>>>(tn, tn, Gt, B_, B_, D_);
    gemm_nt_kernel<<<gnt, 256>>>(vn, tn, Gs, B_, B_, D_);
    hdr_kernel<<<B_, 256>>>();
    galign_kernel<<<2048, 256>>>(labels);

    finalize_kernel<<<1, 1>>>(out);
}

// round 2
// speedup vs baseline: 4.0353x; 4.0353x over previous
#include <cuda_runtime.h>
#include <cuda_bf16.h>
#include <math.h>
#include <float.h>

#define B_ 4096
#define D_ 1024
#define C_ 11003
#define CPAD 11008
#define LSTRIDE 11008
#define SCALE_ 28.0f
#define EPS_LS_ 0.1f
#define T_ 4.0f
#define SPOS_ 10.0f
#define SNEG_ 40.0f
#define ALPHA_ 0.6f
#define BETA_ 0.4f
#define HDR_A_ 3.0f
#define PLEN_ 63
#define LOG_1EM12 -27.631021115928547f

typedef unsigned short ushortt;
typedef unsigned int uintt;

// ---------------- scratch (static device memory; no allocations) ----------------
__device__ ushortt g_vn16[(size_t)B_ * D_];
__device__ ushortt g_tn16[(size_t)B_ * D_];
__device__ ushortt g_W16[(size_t)D_ * CPAD];   // prescaled: 28 * W / colnorm
__device__ ushortt g_Wt16[(size_t)D_ * CPAD];
__device__ float g_sqv[B_];
__device__ float g_sqt[B_];
__device__ float g_logA[(size_t)B_ * LSTRIDE];
__device__ float g_logB[(size_t)B_ * LSTRIDE];
__device__ float g_Gv[(size_t)B_ * B_];
__device__ float g_Gt[(size_t)B_ * B_];
__device__ float g_Gs[(size_t)B_ * B_];
// 0=CE_v 1=CE_t 2=CE_filter 3=dist_f 4=KL 5=HDR 6=GA
__device__ double g_acc[8];

__global__ void zero_acc_kernel() {
    if (threadIdx.x < 8) g_acc[threadIdx.x] = 0.0;
}

// ---------------- prep: normalize rows, emit bf16, squared norms of rounded rows ----
__global__ void normalize_kernel(const float* __restrict__ V, const float* __restrict__ Tm) {
    const int row = blockIdx.x;
    const int tid = threadIdx.x;
    const float* v = V + (size_t)row * D_;
    const float* t = Tm + (size_t)row * D_;

    float vv[4], tt[4];
    float lv = 0.f, lt = 0.f;
#pragma unroll
    for (int i = 0; i < 4; i++) {
        vv[i] = v[tid + 256 * i];
        tt[i] = t[tid + 256 * i];
        lv += vv[i] * vv[i];
        lt += tt[i] * tt[i];
    }
    __shared__ float s1[256], s2[256];
    s1[tid] = lv; s2[tid] = lt;
    __syncthreads();
    for (int s = 128; s > 0; s >>= 1) {
        if (tid < s) { s1[tid] += s1[tid + s]; s2[tid] += s2[tid + s]; }
        __syncthreads();
    }
    const float invv = rsqrtf(s1[0] * s1[0]) * sqrtf(s1[0]); // dummy guard against fusion
    const float iv = 1.0f / sqrtf(s1[0]);
    const float it = 1.0f / sqrtf(s2[0]);
    (void)invv;
    __syncthreads();

    float ld = 0.f, qv = 0.f, qt = 0.f;
#pragma unroll
    for (int i = 0; i < 4; i++) {
        float a = vv[i] * iv;
        float b = tt[i] * it;
        __nv_bfloat16 ha = __float2bfloat16(a);
        __nv_bfloat16 hb = __float2bfloat16(b);
        g_vn16[(size_t)row * D_ + tid + 256 * i] = __bfloat16_as_ushort(ha);
        g_tn16[(size_t)row * D_ + tid + 256 * i] = __bfloat16_as_ushort(hb);
        float af = __bfloat162float(ha);
        float bf = __bfloat162float(hb);
        qv += af * af;
        qt += bf * bf;
        float df = a - b;
        ld += df * df;
    }
    s1[tid] = ld; s2[tid] = qv;
    __syncthreads();
    for (int s = 128; s > 0; s >>= 1) {
        if (tid < s) { s1[tid] += s1[tid + s]; s2[tid] += s2[tid + s]; }
        __syncthreads();
    }
    if (tid == 0) {
        atomicAdd(&g_acc[3], (double)s1[0]);
        g_sqv[row] = s2[0];
    }
    __syncthreads();
    s1[tid] = qt;
    __syncthreads();
    for (int s = 128; s > 0; s >>= 1) {
        if (tid < s) s1[tid] += s1[tid + s];
        __syncthreads();
    }
    if (tid == 0) g_sqt[row] = s1[0];
}

// ---------------- prep: column-normalize W, prescale by 28, emit bf16 (padded) -----
__global__ void colnorm_convert_kernel(const float* __restrict__ W, const float* __restrict__ Wt) {
    const int c = blockIdx.x * blockDim.x + threadIdx.x;
    if (c >= CPAD) return;
    if (c < C_) {
        float s1 = 0.f, s2 = 0.f;
        for (int d = 0; d < D_; d++) {
            float a = W[(size_t)d * C_ + c];
            float b = Wt[(size_t)d * C_ + c];
            s1 += a * a;
            s2 += b * b;
        }
        const float i1 = SCALE_ / sqrtf(s1);
        const float i2 = SCALE_ / sqrtf(s2);
        for (int d = 0; d < D_; d++) {
            g_W16[(size_t)d * CPAD + c] =
                __bfloat16_as_ushort(__float2bfloat16(W[(size_t)d * C_ + c] * i1));
            g_Wt16[(size_t)d * CPAD + c] =
                __bfloat16_as_ushort(__float2bfloat16(Wt[(size_t)d * C_ + c] * i2));
        }
    } else {
        for (int d = 0; d < D_; d++) {
            g_W16[(size_t)d * CPAD + c] = 0;
            g_Wt16[(size_t)d * CPAD + c] = 0;
        }
    }
}

// ---------------- bf16 tensor-core GEMMs ----------------
#define MMA_BF16(dd, aa, bb)                                                     \
    asm volatile(                                                                \
        "mma.sync.aligned.m16n8k16.row.col.f32.bf16.bf16.f32 "                   \
        "{%0,%1,%2,%3}, {%4,%5,%6,%7}, {%8,%9}, {%0,%1,%2,%3};\n"                \
        : "+f"(dd[0]), "+f"(dd[1]), "+f"(dd[2]), "+f"(dd[3])                     \
        : "r"(aa[0]), "r"(aa[1]), "r"(aa[2]), "r"(aa[3]), "r"(bb[0]), "r"(bb[1]))

// NN: Out[4096, C_] (stride LSTRIDE) = A[4096,1024] @ Bm[1024, CPAD]
__global__ void __launch_bounds__(256, 2) gemm_nn_bf16(
    const ushortt* __restrict__ A, const ushortt* __restrict__ Bm, float* __restrict__ Out) {
    __shared__ ushortt As[2][128 * 40];
    __shared__ ushortt Bs[2][32 * 136];
    const int tid = threadIdx.x;
    const int lane = tid & 31, wid = tid >> 5;
    const int g = lane >> 2, tg = lane & 3;
    const int wm = wid & 1, wn = wid >> 1;
    const int rowBase = blockIdx.y * 128, colBase = blockIdx.x * 128;
    const int ar = tid >> 2, ak = (tid & 3) * 8;
    const int br = tid >> 3, bc = (tid & 7) * 16;

    float acc[4][4][4];
#pragma unroll
    for (int i = 0; i < 4; i++)
#pragma unroll
        for (int j = 0; j < 4; j++)
#pragma unroll
            for (int k = 0; k < 4; k++) acc[i][j][k] = 0.f;

    uint4 pa0, pa1, pb0, pb1;
#define NN_LOAD(kt)                                                                        \
    do {                                                                                   \
        pa0 = *(const uint4*)(A + (size_t)(rowBase + ar) * D_ + (kt) + ak);                \
        pa1 = *(const uint4*)(A + (size_t)(rowBase + 64 + ar) * D_ + (kt) + ak);           \
        pb0 = *(const uint4*)(Bm + (size_t)((kt) + br) * CPAD + colBase + bc);             \
        pb1 = *(const uint4*)(Bm + (size_t)((kt) + br) * CPAD + colBase + bc + 8);         \
    } while (0)
#define NN_STORE(bf)                                                                       \
    do {                                                                                   \
        *(uint4*)&As[bf][ar * 40 + ak] = pa0;                                              \
        *(uint4*)&As[bf][(64 + ar) * 40 + ak] = pa1;                                       \
        *(uint4*)&Bs[bf][br * 136 + bc] = pb0;                                             \
        *(uint4*)&Bs[bf][br * 136 + bc + 8] = pb1;                                         \
    } while (0)

    NN_LOAD(0);
    NN_STORE(0);
    __syncthreads();

    for (int chunk = 0; chunk < 32; chunk++) {
        const int buf = chunk & 1;
        if (chunk < 31) NN_LOAD((chunk + 1) * 32);
#pragma unroll
        for (int ks = 0; ks < 2; ks++) {
            const int k0 = ks * 16;
            uintt a[4][4], b[4][2];
#pragma unroll
            for (int mt = 0; mt < 4; mt++) {
                const ushortt* p = &As[buf][(wm * 64 + mt * 16 + g) * 40 + k0 + tg * 2];
                a[mt][0] = *(const uintt*)(p);
                a[mt][1] = *(const uintt*)(p + 8 * 40);
                a[mt][2] = *(const uintt*)(p + 8);
                a[mt][3] = *(const uintt*)(p + 8 * 40 + 8);
            }
#pragma unroll
            for (int nt = 0; nt < 4; nt++) {
                const ushortt* p = &Bs[buf][(k0 + tg * 2) * 136 + wn * 32 + nt * 8 + g];
                b[nt][0] = (uintt)p[0] | ((uintt)p[136] << 16);
                b[nt][1] = (uintt)p[8 * 136] | ((uintt)p[9 * 136] << 16);
            }
#pragma unroll
            for (int mt = 0; mt < 4; mt++)
#pragma unroll
                for (int nt = 0; nt < 4; nt++) MMA_BF16(acc[mt][nt], a[mt], b[nt]);
        }
        if (chunk < 31) NN_STORE(buf ^ 1);
        __syncthreads();
    }

#pragma unroll
    for (int mt = 0; mt < 4; mt++) {
        const int row = rowBase + wm * 64 + mt * 16 + g;
#pragma unroll
        for (int nt = 0; nt < 4; nt++) {
            const int col = colBase + wn * 32 + nt * 8 + tg * 2;
            float* o0 = Out + (size_t)row * LSTRIDE + col;
            float* o1 = o0 + (size_t)8 * LSTRIDE;
            if (col + 1 < C_) {
                *(float2*)o0 = make_float2(acc[mt][nt][0], acc[mt][nt][1]);
                *(float2*)o1 = make_float2(acc[mt][nt][2], acc[mt][nt][3]);
            } else if (col < C_) {
                *o0 = acc[mt][nt][0];
                *o1 = acc[mt][nt][2];
            }
        }
    }
}

// NT: Out[4096,4096] = A[4096,1024] @ Bsrc[4096,1024]^T
__global__ void __launch_bounds__(256, 2) gemm_nt_bf16(
    const ushortt* __restrict__ A, const ushortt* __restrict__ Bsrc, float* __restrict__ Out) {
    __shared__ ushortt As[2][128 * 40];
    __shared__ ushortt Bs[2][128 * 40];
    const int tid = threadIdx.x;
    const int lane = tid & 31, wid = tid >> 5;
    const int g = lane >> 2, tg = lane & 3;
    const int wm = wid & 1, wn = wid >> 1;
    const int rowBase = blockIdx.y * 128, colBase = blockIdx.x * 128;
    const int ar = tid >> 2, ak = (tid & 3) * 8;

    float acc[4][4][4];
#pragma unroll
    for (int i = 0; i < 4; i++)
#pragma unroll
        for (int j = 0; j < 4; j++)
#pragma unroll
            for (int k = 0; k < 4; k++) acc[i][j][k] = 0.f;

    uint4 pa0, pa1, pb0, pb1;
#define NT_LOAD(kt)                                                                       \
    do {                                                                                  \
        pa0 = *(const uint4*)(A + (size_t)(rowBase + ar) * D_ + (kt) + ak);               \
        pa1 = *(const uint4*)(A + (size_t)(rowBase + 64 + ar) * D_ + (kt) + ak);          \
        pb0 = *(const uint4*)(Bsrc + (size_t)(colBase + ar) * D_ + (kt) + ak);            \
        pb1 = *(const uint4*)(Bsrc + (size_t)(colBase + 64 + ar) * D_ + (kt) + ak);       \
    } while (0)
#define NT_STORE(bf)                                                                      \
    do {                                                                                  \
        *(uint4*)&As[bf][ar * 40 + ak] = pa0;                                             \
        *(uint4*)&As[bf][(64 + ar) * 40 + ak] = pa1;                                      \
        *(uint4*)&Bs[bf][ar * 40 + ak] = pb0;                                             \
        *(uint4*)&Bs[bf][(64 + ar) * 40 + ak] = pb1;                                      \
    } while (0)

    NT_LOAD(0);
    NT_STORE(0);
    __syncthreads();

    for (int chunk = 0; chunk < 32; chunk++) {
        const int buf = chunk & 1;
        if (chunk < 31) NT_LOAD((chunk + 1) * 32);
#pragma unroll
        for (int ks = 0; ks < 2; ks++) {
            const int k0 = ks * 16;
            uintt a[4][4], b[4][2];
#pragma unroll
            for (int mt = 0; mt < 4; mt++) {
                const ushortt* p = &As[buf][(wm * 64 + mt * 16 + g) * 40 + k0 + tg * 2];
                a[mt][0] = *(const uintt*)(p);
                a[mt][1] = *(const uintt*)(p + 8 * 40);
                a[mt][2] = *(const uintt*)(p + 8);
                a[mt][3] = *(const uintt*)(p + 8 * 40 + 8);
            }
#pragma unroll
            for (int nt = 0; nt < 4; nt++) {
                const ushortt* p = &Bs[buf][(wn * 32 + nt * 8 + g) * 40 + k0 + tg * 2];
                b[nt][0] = *(const uintt*)(p);
                b[nt][1] = *(const uintt*)(p + 8);
            }
#pragma unroll
            for (int mt = 0; mt < 4; mt++)
#pragma unroll
                for (int nt = 0; nt < 4; nt++) MMA_BF16(acc[mt][nt], a[mt], b[nt]);
        }
        if (chunk < 31) NT_STORE(buf ^ 1);
        __syncthreads();
    }

#pragma unroll
    for (int mt = 0; mt < 4; mt++) {
        const int row = rowBase + wm * 64 + mt * 16 + g;
#pragma unroll
        for (int nt = 0; nt < 4; nt++) {
            const int col = colBase + wn * 32 + nt * 8 + tg * 2;
            float* o0 = Out + (size_t)row * B_ + col;
            *(float2*)o0 = make_float2(acc[mt][nt][0], acc[mt][nt][1]);
            *(float2*)(o0 + (size_t)8 * B_) = make_float2(acc[mt][nt][2], acc[mt][nt][3]);
        }
    }
}

// ---------------- losses ----------------
// Label-smoothed CE, single pass (|logit| <= 28 so the softmax shift is fixed at 28).
__global__ void ce_kernel(const float* __restrict__ logits, const int* __restrict__ labels,
                          int accIdx) {
    const int row = blockIdx.x;
    const int tid = threadIdx.x;
    const float* x = logits + (size_t)row * LSTRIDE;
    __shared__ float s1[256], s2[256];

    float se = 0.f, sx = 0.f;
    for (int c = tid; c < C_; c += 256) {
        float v = x[c];
        se += expf(v - SCALE_);
        sx += v;
    }
    s1[tid] = se; s2[tid] = sx;
    __syncthreads();
    for (int s = 128; s > 0; s >>= 1) {
        if (tid < s) { s1[tid] += s1[tid + s]; s2[tid] += s2[tid + s]; }
        __syncthreads();
    }
    if (tid == 0) {
        float lse = SCALE_ + logf(s1[0]);
        float picked = x[labels[row]];
        double ce = -((1.0 - (double)EPS_LS_) * ((double)picked - lse) +
                      ((double)EPS_LS_ / C_) * ((double)s2[0] - (double)C_ * lse));
        atomicAdd(&g_acc[accIdx], ce);
    }
}

// KL(teacher=visual, student=textual) at temperature T. Fixed shift 28/T.
__global__ void kl_kernel(const float* __restrict__ teach, const float* __restrict__ stud) {
    const int row = blockIdx.x;
    const int tid = threadIdx.x;
    const float* xt = teach + (size_t)row * LSTRIDE;
    const float* xs = stud + (size_t)row * LSTRIDE;
    __shared__ float s1[256], s2[256];
    const float SH = SCALE_ / T_;

    float set = 0.f, ses = 0.f;
    for (int c = tid; c < C_; c += 256) {
        set += expf(xt[c] / T_ - SH);
        ses += expf(xs[c] / T_ - SH);
    }
    s1[tid] = set; s2[tid] = ses;
    __syncthreads();
    for (int s = 128; s > 0; s >>= 1) {
        if (tid < s) { s1[tid] += s1[tid + s]; s2[tid] += s2[tid + s]; }
        __syncthreads();
    }
    const float lse_t = SH + logf(s1[0]);
    const float lse_s = SH + logf(s2[0]);
    __syncthreads();

    float acc = 0.f;
    for (int c = tid; c < C_; c += 256) {
        float lt = xt[c] / T_ - lse_t;
        float ls = xs[c] / T_ - lse_s;
        float tprob = expf(lt);
        float ltc = fmaxf(lt, LOG_1EM12);
        float lsc = fmaxf(ls, LOG_1EM12);
        acc += tprob * (ltc - lsc);
    }
    s1[tid] = acc;
    __syncthreads();
    for (int s = 128; s > 0; s >>= 1) {
        if (tid < s) s1[tid] += s1[tid + s];
        __syncthreads();
    }
    if (tid == 0) atomicAdd(&g_acc[4], (double)s1[0]);
}

// HardDarkRank
__global__ void hdr_kernel() {
    const int row = blockIdx.x;
    const int tid = threadIdx.x;
    __shared__ float score[B_];
    __shared__ float sv[256];
    __shared__ int si[256];
    __shared__ int idxs[PLEN_];
    __shared__ float ord[PLEN_];

    const float sq_r = g_sqv[row];
    for (int j = tid; j < B_; j += 256) {
        float gg = g_Gv[(size_t)row * B_ + j];
        float d2 = fmaxf(sq_r + g_sqv[j] - 2.0f * gg, 1e-12f);
        float d = sqrtf(d2);
        score[j] = (j == row) ? -FLT_MAX : (-HDR_A_ * d * d * d);
    }
    __syncthreads();

    for (int k = 0; k < PLEN_; k++) {
        float best = -FLT_MAX;
        int bidx = 0x7fffffff;
        for (int j = tid; j < B_; j += 256) {
            float v = score[j];
            if (v > best || (v == best && j < bidx)) { best = v; bidx = j; }
        }
        sv[tid] = best; si[tid] = bidx;
        __syncthreads();
        for (int s = 128; s > 0; s >>= 1) {
            if (tid < s) {
                float ov = sv[tid + s]; int oi = si[tid + s];
                if (ov > sv[tid] || (ov == sv[tid] && oi < si[tid])) { sv[tid] = ov; si[tid] = oi; }
            }
            __syncthreads();
        }
        if (tid == 0) {
            idxs[k] = si[0];
            score[si[0]] = -FLT_MAX;
        }
        __syncthreads();
    }

    const float sqt_r = g_sqt[row];
    if (tid < PLEN_) {
        int j = idxs[tid];
        float gg = g_Gt[(size_t)row * B_ + j];
        float d2 = fmaxf(sqt_r + g_sqt[j] - 2.0f * gg, 1e-12f);
        float d = sqrtf(d2);
        ord[tid] = -HDR_A_ * d * d * d;
    }
    __syncthreads();
    if (tid == 0) {
        float acc = -FLT_MAX;
        float total = 0.f;
        for (int k = PLEN_ - 1; k >= 0; k--) {
            float o = ord[k];
            if (acc == -FLT_MAX) acc = o;
            else {
                float mx = fmaxf(acc, o);
                acc = mx + log1pf(expf(fminf(acc, o) - mx));
            }
            total += o - acc;
        }
        atomicAdd(&g_acc[5], (double)(-total));
    }
}

// Global align over sim = vn @ tn^T
__global__ void galign_kernel(const int* __restrict__ labels) {
    const int tid = threadIdx.x;
    const size_t stride = (size_t)gridDim.x * blockDim.x;
    double local = 0.0;
    for (size_t e = (size_t)blockIdx.x * blockDim.x + tid; e < (size_t)B_ * B_; e += stride) {
        int i = (int)(e >> 12);
        int j = (int)(e & 4095);
        float sim = g_Gs[e];
        bool same = labels[i] == labels[j];
        float x = same ? (-SPOS_ * (sim - ALPHA_)) : (SNEG_ * (sim - BETA_));
        local += (double)log1pf(expf(x));
    }
    __shared__ double sd[256];
    sd[tid] = local;
    __syncthreads();
    for (int s = 128; s > 0; s >>= 1) {
        if (tid < s) sd[tid] += sd[tid + s];
        __syncthreads();
    }
    if (tid == 0) atomicAdd(&g_acc[6], sd[0]);
}

__global__ void finalize_kernel(float* out) {
    const double invB = 1.0 / (double)B_;
    double v = (g_acc[0] + g_acc[1] + g_acc[2]) * invB
             + g_acc[3] * invB
             + g_acc[4] * invB
             + 0.1 * g_acc[5] * invB
             + 2.0 * g_acc[6] * invB;
    out[0] = (float)v;
}

// ---------------- launch ----------------
extern "C" void kernel_launch(void* const* d_in, const int* in_sizes, int n_in,
                              void* d_out, int out_size) {
    const float* V = (const float*)d_in[0];
    const float* Tx = (const float*)d_in[1];
    const int* labels = (const int*)d_in[2];
    const float* W = (const float*)d_in[3];
    const float* Wt = (const float*)d_in[4];
    float* out = (float*)d_out;

    ushortt *vn16, *tn16, *W16, *Wt16;
    float *logA, *logB, *Gv, *Gt, *Gs;
    cudaGetSymbolAddress((void**)&vn16, g_vn16);
    cudaGetSymbolAddress((void**)&tn16, g_tn16);
    cudaGetSymbolAddress((void**)&W16, g_W16);
    cudaGetSymbolAddress((void**)&Wt16, g_Wt16);
    cudaGetSymbolAddress((void**)&logA, g_logA);
    cudaGetSymbolAddress((void**)&logB, g_logB);
    cudaGetSymbolAddress((void**)&Gv, g_Gv);
    cudaGetSymbolAddress((void**)&Gt, g_Gt);
    cudaGetSymbolAddress((void**)&Gs, g_Gs);

    zero_acc_kernel<<<1, 32>>>();
    normalize_kernel<<<B_, 256>>>(V, Tx);
    colnorm_convert_kernel<<<(CPAD + 255) / 256, 256>>>(W, Wt);

    dim3 gnn(CPAD / 128, B_ / 128);
    gemm_nn_bf16<<<gnn, 256>>>(vn16, W16, logA);   // visual logits
    gemm_nn_bf16<<<gnn, 256>>>(tn16, W16, logB);   // textual logits
    ce_kernel<<<B_, 256>>>(logA, labels, 0);
    ce_kernel<<<B_, 256>>>(logB, labels, 1);
    kl_kernel<<<B_, 256>>>(logA, logB);
    gemm_nn_bf16<<<gnn, 256>>>(tn16, Wt16, logA);  // filter logits (reuse logA)
    ce_kernel<<<B_, 256>>>(logA, labels, 2);

    dim3 gnt(B_ / 128, B_ / 128);
    gemm_nt_bf16<<<gnt, 256>>>(vn16, vn16, Gv);
    gemm_nt_bf16<<<gnt, 256>>>(tn16, tn16, Gt);
    gemm_nt_bf16<<<gnt, 256>>>(vn16, tn16, Gs);
    hdr_kernel<<<B_, 256>>>();
    galign_kernel<<<2048, 256>>>(labels);

    finalize_kernel<<<1, 1>>>(out);
}

// round 6
// speedup vs baseline: 5.8350x; 1.4460x over previous
#include <cuda_runtime.h>
#include <cuda_bf16.h>
#include <stdint.h>
#include <math.h>
#include <float.h>

#define B_ 4096
#define D_ 1024
#define C_ 11003
#define CPAD 11008
#define LSTRIDE 11008
#define SCALE_ 28.0f
#define EPS_LS_ 0.1f
#define T_ 4.0f
#define SPOS_ 10.0f
#define SNEG_ 40.0f
#define ALPHA_ 0.6f
#define BETA_ 0.4f
#define HDR_A_ 3.0f
#define PLEN_ 63

typedef unsigned short ushortt;

// ---------------- scratch ----------------
__device__ ushortt g_vn16[(size_t)B_ * D_];
__device__ ushortt g_tn16[(size_t)B_ * D_];
__device__ ushortt g_W16t[(size_t)CPAD * D_];   // transposed, prescaled 28/colnorm
__device__ ushortt g_Wt16t[(size_t)CPAD * D_];
__device__ float g_invW[CPAD];
__device__ float g_invWt[CPAD];
__device__ float g_sqv[B_];
__device__ float g_sqt[B_];
__device__ float g_logA[(size_t)B_ * LSTRIDE];
__device__ float g_logB[(size_t)B_ * LSTRIDE];
__device__ float g_Gv[(size_t)B_ * B_];
__device__ float g_Gt[(size_t)B_ * B_];
__device__ float g_Gs[(size_t)B_ * B_];
// 0=CE_v 1=CE_t 2=CE_filter 3=dist_f 4=KL 5=HDR 6=GA
__device__ double g_acc[8];

__global__ void zero_acc_kernel() {
    if (threadIdx.x < 8) g_acc[threadIdx.x] = 0.0;
}

// ---------------- PTX helpers ----------------
__device__ __forceinline__ uint32_t smem_u32(const void* p) {
    return (uint32_t)__cvta_generic_to_shared((void*)p);
}
#define CP_ASYNC16(dst, src) \
    asm volatile("cp.async.cg.shared.global [%0], [%1], 16;\n" :: "r"(dst), "l"(src))
#define CP_COMMIT() asm volatile("cp.async.commit_group;\n" ::: "memory")
#define CP_WAIT(N) asm volatile("cp.async.wait_group %0;\n" :: "n"(N) : "memory")

#define LDSM4(d0, d1, d2, d3, a) \
    asm volatile("ldmatrix.sync.aligned.m8n8.x4.shared.b16 {%0,%1,%2,%3}, [%4];" \
                 : "=r"(d0), "=r"(d1), "=r"(d2), "=r"(d3) : "r"(a))

#define MMA_BF16(dd, aa, bb)                                                     \
    asm volatile(                                                                \
        "mma.sync.aligned.m16n8k16.row.col.f32.bf16.bf16.f32 "                   \
        "{%0,%1,%2,%3}, {%4,%5,%6,%7}, {%8,%9}, {%0,%1,%2,%3};\n"                \
        : "+f"(dd[0]), "+f"(dd[1]), "+f"(dd[2]), "+f"(dd[3])                     \
        : "r"(aa[0]), "r"(aa[1]), "r"(aa[2]), "r"(aa[3]), "r"(bb[0]), "r"(bb[1]))

#define SWZ(off) ((off) ^ (((off) >> 3) & 0x70))

// ---------------- HMMA GEMM: Out[M,N](ldOut) = A[M,K] @ B[N,K]^T, bf16 in fp32 out --------
// Tiles: CTA 128x128, BK=64, 8 warps (2m x 4n, warp tile 64x32), 3-stage cp.async.
// NOTE: k-step advance on swizzled addresses is XOR (bits 5-6 disjoint from the
// 16B sub-tile selector bit 4), NOT addition — addition carries into the row field.
#define BKB 128                 // bytes per tile row (64 bf16)
#define A_STG 16384             // 128 rows * 128B
#define STG_BYTES 32768         // A + B per stage
#define NSTG 3

__global__ void __launch_bounds__(256, 2) gemm_hmma(
    const ushortt* __restrict__ A, const ushortt* __restrict__ Bsrc,
    float* __restrict__ Out, int ldOut) {
    extern __shared__ char sm[];
    const uint32_t smBase = smem_u32(sm);

    const int tid = threadIdx.x;
    const int lane = tid & 31, w = tid >> 5;
    const int wm = w & 1, wn = w >> 1;
    const int g = lane >> 2, tg = lane & 3;
    const int rowBase = blockIdx.y * 128, colBase = blockIdx.x * 128;

    // ---- cp.async mapping: 4 x 16B per thread per operand per stage ----
    uint32_t stA[4], stB[4];           // swizzled smem offsets (within stage)
    const ushortt* srcA[4];
    const ushortt* srcB[4];
#pragma unroll
    for (int i = 0; i < 4; i++) {
        int idx = i * 256 + tid;
        int row = idx >> 3, ch = idx & 7;
        uint32_t off = row * BKB + ch * 16;
        stA[i] = SWZ(off);
        stB[i] = SWZ(off) + A_STG;
        srcA[i] = A + (size_t)(rowBase + row) * D_ + ch * 8;
        srcB[i] = Bsrc + (size_t)(colBase + row) * D_ + ch * 8;
    }

    // ---- ldmatrix lane addresses (swizzled, k-step 0) ----
    // A: per mt, matrices {m0-7,k0-7},{m8-15,k0-7},{m0-7,k8-15},{m8-15,k8-15}
    uint32_t aAddr[4];
    {
        int grp = lane >> 3, r = lane & 7;
#pragma unroll
        for (int mt = 0; mt < 4; mt++) {
            int row = wm * 64 + mt * 16 + (grp & 1) * 8 + r;
            uint32_t off = row * BKB + (grp >> 1) * 16;
            aAddr[mt] = SWZ(off);
        }
    }
    // B: per h (0,1): matrices {n0-7,k0-7},{n0-7,k8-15},{n8-15,k0-7},{n8-15,k8-15}
    uint32_t bAddr[2];
    {
        int grp = lane >> 3, r = lane & 7;
#pragma unroll
        for (int h = 0; h < 2; h++) {
            int row = wn * 32 + h * 16 + (grp >> 1) * 8 + r;
            uint32_t off = row * BKB + (grp & 1) * 16;
            bAddr[h] = SWZ(off) + A_STG;
        }
    }

    float acc[4][4][4];
#pragma unroll
    for (int i = 0; i < 4; i++)
#pragma unroll
        for (int j = 0; j < 4; j++)
#pragma unroll
            for (int k = 0; k < 4; k++) acc[i][j][k] = 0.f;

    auto load_stage = [&](int kc, int stg) {
        const uint32_t base = smBase + stg * STG_BYTES;
        const int k0 = kc * 64;
#pragma unroll
        for (int i = 0; i < 4; i++) CP_ASYNC16(base + stA[i], srcA[i] + k0);
#pragma unroll
        for (int i = 0; i < 4; i++) CP_ASYNC16(base + stB[i], srcB[i] + k0);
    };

    load_stage(0, 0); CP_COMMIT();
    load_stage(1, 1); CP_COMMIT();

#pragma unroll 1
    for (int c = 0; c < 16; c++) {
        const int stg = c % NSTG;
        if (c < 14) { CP_WAIT(1); } else { CP_WAIT(0); }
        __syncthreads();
        if (c + 2 < 16) { load_stage(c + 2, (c + 2) % NSTG); CP_COMMIT(); }

        const uint32_t base = smBase + stg * STG_BYTES;
#pragma unroll
        for (int ks = 0; ks < 4; ks++) {
            const uint32_t kx = ks * 32;   // XOR-step within the 128B swizzled row
            uint32_t a[4][4], b[4][2];
#pragma unroll
            for (int mt = 0; mt < 4; mt++)
                LDSM4(a[mt][0], a[mt][1], a[mt][2], a[mt][3], base + (aAddr[mt] ^ kx));
#pragma unroll
            for (int h = 0; h < 2; h++)
                LDSM4(b[2 * h][0], b[2 * h][1], b[2 * h + 1][0], b[2 * h + 1][1],
                      base + (bAddr[h] ^ kx));
#pragma unroll
            for (int mt = 0; mt < 4; mt++)
#pragma unroll
                for (int nt = 0; nt < 4; nt++) MMA_BF16(acc[mt][nt], a[mt], b[nt]);
        }
    }

    // ---- epilogue (Out always padded wide enough; no guards) ----
#pragma unroll
    for (int mt = 0; mt < 4; mt++) {
        const int row = rowBase + wm * 64 + mt * 16 + g;
#pragma unroll
        for (int nt = 0; nt < 4; nt++) {
            const int col = colBase + wn * 32 + nt * 8 + tg * 2;
            float* o0 = Out + (size_t)row * ldOut + col;
            *(float2*)o0 = make_float2(acc[mt][nt][0], acc[mt][nt][1]);
            *(float2*)(o0 + (size_t)8 * ldOut) = make_float2(acc[mt][nt][2], acc[mt][nt][3]);
        }
    }
}

// ---------------- prep kernels ----------------
__global__ void normalize_kernel(const float* __restrict__ V, const float* __restrict__ Tm) {
    const int row = blockIdx.x;
    const int tid = threadIdx.x;
    const float* v = V + (size_t)row * D_;
    const float* t = Tm + (size_t)row * D_;

    float vv[4], tt[4];
    float lv = 0.f, lt = 0.f;
#pragma unroll
    for (int i = 0; i < 4; i++) {
        vv[i] = v[tid + 256 * i];
        tt[i] = t[tid + 256 * i];
        lv += vv[i] * vv[i];
        lt += tt[i] * tt[i];
    }
    __shared__ float s1[256], s2[256];
    s1[tid] = lv; s2[tid] = lt;
    __syncthreads();
    for (int s = 128; s > 0; s >>= 1) {
        if (tid < s) { s1[tid] += s1[tid + s]; s2[tid] += s2[tid + s]; }
        __syncthreads();
    }
    const float iv = 1.0f / sqrtf(s1[0]);
    const float it = 1.0f / sqrtf(s2[0]);
    __syncthreads();

    float ld = 0.f, qv = 0.f, qt = 0.f;
#pragma unroll
    for (int i = 0; i < 4; i++) {
        float a = vv[i] * iv;
        float b = tt[i] * it;
        __nv_bfloat16 ha = __float2bfloat16(a);
        __nv_bfloat16 hb = __float2bfloat16(b);
        g_vn16[(size_t)row * D_ + tid + 256 * i] = __bfloat16_as_ushort(ha);
        g_tn16[(size_t)row * D_ + tid + 256 * i] = __bfloat16_as_ushort(hb);
        float af = __bfloat162float(ha);
        float bf = __bfloat162float(hb);
        qv += af * af;
        qt += bf * bf;
        float df = a - b;
        ld += df * df;
    }
    s1[tid] = ld; s2[tid] = qv;
    __syncthreads();
    for (int s = 128; s > 0; s >>= 1) {
        if (tid < s) { s1[tid] += s1[tid + s]; s2[tid] += s2[tid + s]; }
        __syncthreads();
    }
    if (tid == 0) {
        atomicAdd(&g_acc[3], (double)s1[0]);
        g_sqv[row] = s2[0];
    }
    __syncthreads();
    s1[tid] = qt;
    __syncthreads();
    for (int s = 128; s > 0; s >>= 1) {
        if (tid < s) s1[tid] += s1[tid + s];
        __syncthreads();
    }
    if (tid == 0) g_sqt[row] = s1[0];
}

__global__ void colnorm_kernel(const float* __restrict__ W, const float* __restrict__ Wt) {
    const int c = blockIdx.x * blockDim.x + threadIdx.x;
    if (c >= CPAD) return;
    if (c < C_) {
        float s1 = 0.f, s2 = 0.f;
        for (int d = 0; d < D_; d++) {
            float a = W[(size_t)d * C_ + c];
            float b = Wt[(size_t)d * C_ + c];
            s1 += a * a;
            s2 += b * b;
        }
        g_invW[c] = SCALE_ / sqrtf(s1);
        g_invWt[c] = SCALE_ / sqrtf(s2);
    } else {
        g_invW[c] = 0.f;
        g_invWt[c] = 0.f;
    }
}

// 32x32 tile transpose W[d][c] -> W16t[c][d] (scaled, bf16), both matrices.
__global__ void transpose_convert_kernel(const float* __restrict__ W, const float* __restrict__ Wt) {
    __shared__ float t1[32][33];
    __shared__ float t2[32][33];
    const int c0 = blockIdx.x * 32, d0 = blockIdx.y * 32;
    const int tx = threadIdx.x, ty = threadIdx.y;
#pragma unroll
    for (int i = 0; i < 4; i++) {
        int d = d0 + ty + i * 8;
        int c = c0 + tx;
        float v1 = 0.f, v2 = 0.f;
        if (c < C_) {
            v1 = W[(size_t)d * C_ + c] * g_invW[c];
            v2 = Wt[(size_t)d * C_ + c] * g_invWt[c];
        }
        t1[ty + i * 8][tx] = v1;
        t2[ty + i * 8][tx] = v2;
    }
    __syncthreads();
#pragma unroll
    for (int i = 0; i < 4; i++) {
        int c = c0 + ty + i * 8;
        int d = d0 + tx;
        g_W16t[(size_t)c * D_ + d] = __bfloat16_as_ushort(__float2bfloat16(t1[tx][ty + i * 8]));
        g_Wt16t[(size_t)c * D_ + d] = __bfloat16_as_ushort(__float2bfloat16(t2[tx][ty + i * 8]));
    }
}

// ---------------- fused CE_v + CE_t + KL, single pass ----------------
__global__ void vt_loss_kernel(const float* __restrict__ logA, const float* __restrict__ logB,
                               const int* __restrict__ labels) {
    const int row = blockIdx.x;
    const int tid = threadIdx.x;
    const float* xA = logA + (size_t)row * LSTRIDE;
    const float* xB = logB + (size_t)row * LSTRIDE;

    float sA = 0.f, sxA = 0.f, sB = 0.f, sxB = 0.f, zT = 0.f, zS = 0.f, wd = 0.f;
    for (int c = tid; c < C_; c += 256) {
        float a = xA[c], b = xB[c];
        sA += __expf(a - SCALE_);
        sB += __expf(b - SCALE_);
        float ea = __expf(a * 0.25f - 7.f);
        float eb = __expf(b * 0.25f - 7.f);
        zT += ea; zS += eb;
        wd += ea * (a - b);
        sxA += a; sxB += b;
    }
    float vals[7] = {sA, sxA, sB, sxB, zT, zS, wd};
#pragma unroll
    for (int q = 0; q < 7; q++)
#pragma unroll
        for (int o = 16; o > 0; o >>= 1) vals[q] += __shfl_xor_sync(0xffffffffu, vals[q], o);
    __shared__ float red[8][7];
    if ((tid & 31) == 0)
#pragma unroll
        for (int q = 0; q < 7; q++) red[tid >> 5][q] = vals[q];
    __syncthreads();
    if (tid == 0) {
        double r[7];
        for (int q = 0; q < 7; q++) {
            double s = 0.0;
            for (int k = 0; k < 8; k++) s += (double)red[k][q];
            r[q] = s;
        }
        const int lab = labels[row];
        double lseA = (double)SCALE_ + log(r[0]);
        double lseB = (double)SCALE_ + log(r[2]);
        double ceA = -((1.0 - (double)EPS_LS_) * ((double)xA[lab] - lseA) +
                       ((double)EPS_LS_ / C_) * (r[1] - (double)C_ * lseA));
        double ceB = -((1.0 - (double)EPS_LS_) * ((double)xB[lab] - lseB) +
                       ((double)EPS_LS_ / C_) * (r[3] - (double)C_ * lseB));
        double kl = r[6] / ((double)T_ * r[4]) + log(r[5]) - log(r[4]);
        atomicAdd(&g_acc[0], ceA);
        atomicAdd(&g_acc[1], ceB);
        atomicAdd(&g_acc[4], kl);
    }
}

__global__ void ce_kernel(const float* __restrict__ logits, const int* __restrict__ labels,
                          int accIdx) {
    const int row = blockIdx.x;
    const int tid = threadIdx.x;
    const float* x = logits + (size_t)row * LSTRIDE;
    float se = 0.f, sx = 0.f;
    for (int c = tid; c < C_; c += 256) {
        float v = x[c];
        se += __expf(v - SCALE_);
        sx += v;
    }
#pragma unroll
    for (int o = 16; o > 0; o >>= 1) {
        se += __shfl_xor_sync(0xffffffffu, se, o);
        sx += __shfl_xor_sync(0xffffffffu, sx, o);
    }
    __shared__ float r1[8], r2[8];
    if ((tid & 31) == 0) { r1[tid >> 5] = se; r2[tid >> 5] = sx; }
    __syncthreads();
    if (tid == 0) {
        double s1 = 0.0, s2 = 0.0;
        for (int k = 0; k < 8; k++) { s1 += (double)r1[k]; s2 += (double)r2[k]; }
        double lse = (double)SCALE_ + log(s1);
        double ce = -((1.0 - (double)EPS_LS_) * ((double)x[labels[row]] - lse) +
                      ((double)EPS_LS_ / C_) * (s2 - (double)C_ * lse));
        atomicAdd(&g_acc[accIdx], ce);
    }
}

// ---------------- HardDarkRank ----------------
__global__ void hdr_kernel() {
    const int row = blockIdx.x;
    const int tid = threadIdx.x;
    __shared__ float score[B_];
    __shared__ float sv[256];
    __shared__ int si[256];
    __shared__ int idxs[PLEN_];
    __shared__ float ord[PLEN_];

    const float sq_r = g_sqv[row];
    for (int j = tid; j < B_; j += 256) {
        float gg = g_Gv[(size_t)row * B_ + j];
        float d2 = fmaxf(sq_r + g_sqv[j] - 2.0f * gg, 1e-12f);
        float d = sqrtf(d2);
        score[j] = (j == row) ? -FLT_MAX : (-HDR_A_ * d * d * d);
    }
    __syncthreads();

    for (int k = 0; k < PLEN_; k++) {
        float best = -FLT_MAX;
        int bidx = 0x7fffffff;
        for (int j = tid; j < B_; j += 256) {
            float v = score[j];
            if (v > best || (v == best && j < bidx)) { best = v; bidx = j; }
        }
        sv[tid] = best; si[tid] = bidx;
        __syncthreads();
        for (int s = 128; s > 0; s >>= 1) {
            if (tid < s) {
                float ov = sv[tid + s]; int oi = si[tid + s];
                if (ov > sv[tid] || (ov == sv[tid] && oi < si[tid])) { sv[tid] = ov; si[tid] = oi; }
            }
            __syncthreads();
        }
        if (tid == 0) {
            idxs[k] = si[0];
            score[si[0]] = -FLT_MAX;
        }
        __syncthreads();
    }

    const float sqt_r = g_sqt[row];
    if (tid < PLEN_) {
        int j = idxs[tid];
        float gg = g_Gt[(size_t)row * B_ + j];
        float d2 = fmaxf(sqt_r + g_sqt[j] - 2.0f * gg, 1e-12f);
        float d = sqrtf(d2);
        ord[tid] = -HDR_A_ * d * d * d;
    }
    __syncthreads();
    if (tid == 0) {
        float acc = -FLT_MAX;
        float total = 0.f;
        for (int k = PLEN_ - 1; k >= 0; k--) {
            float o = ord[k];
            if (acc == -FLT_MAX) acc = o;
            else {
                float mx = fmaxf(acc, o);
                acc = mx + log1pf(__expf(fminf(acc, o) - mx));
            }
            total += o - acc;
        }
        atomicAdd(&g_acc[5], (double)(-total));
    }
}

// ---------------- global align ----------------
__global__ void galign_kernel(const int* __restrict__ labels) {
    const int tid = threadIdx.x;
    const size_t stride = (size_t)gridDim.x * blockDim.x;
    double local = 0.0;
    for (size_t e = (size_t)blockIdx.x * blockDim.x + tid; e < (size_t)B_ * B_; e += stride) {
        int i = (int)(e >> 12);
        int j = (int)(e & 4095);
        float sim = g_Gs[e];
        bool same = labels[i] == labels[j];
        float x = same ? (-SPOS_ * (sim - ALPHA_)) : (SNEG_ * (sim - BETA_));
        local += (double)log1pf(__expf(x));
    }
    __shared__ double sd[256];
    sd[tid] = local;
    __syncthreads();
    for (int s = 128; s > 0; s >>= 1) {
        if (tid < s) sd[tid] += sd[tid + s];
        __syncthreads();
    }
    if (tid == 0) atomicAdd(&g_acc[6], sd[0]);
}

__global__ void finalize_kernel(float* out) {
    const double invB = 1.0 / (double)B_;
    double v = (g_acc[0] + g_acc[1] + g_acc[2]) * invB
             + g_acc[3] * invB
             + g_acc[4] * invB
             + 0.1 * g_acc[5] * invB
             + 2.0 * g_acc[6] * invB;
    out[0] = (float)v;
}

// ---------------- launch ----------------
extern "C" void kernel_launch(void* const* d_in, const int* in_sizes, int n_in,
                              void* d_out, int out_size) {
    const float* V = (const float*)d_in[0];
    const float* Tx = (const float*)d_in[1];
    const int* labels = (const int*)d_in[2];
    const float* W = (const float*)d_in[3];
    const float* Wt = (const float*)d_in[4];
    float* out = (float*)d_out;

    ushortt *vn16, *tn16, *W16t, *Wt16t;
    float *logA, *logB, *Gv, *Gt, *Gs;
    cudaGetSymbolAddress((void**)&vn16, g_vn16);
    cudaGetSymbolAddress((void**)&tn16, g_tn16);
    cudaGetSymbolAddress((void**)&W16t, g_W16t);
    cudaGetSymbolAddress((void**)&Wt16t, g_Wt16t);
    cudaGetSymbolAddress((void**)&logA, g_logA);
    cudaGetSymbolAddress((void**)&logB, g_logB);
    cudaGetSymbolAddress((void**)&Gv, g_Gv);
    cudaGetSymbolAddress((void**)&Gt, g_Gt);
    cudaGetSymbolAddress((void**)&Gs, g_Gs);

    const int DSMEM = NSTG * STG_BYTES;   // 98304
    cudaFuncSetAttribute(gemm_hmma, cudaFuncAttributeMaxDynamicSharedMemorySize, DSMEM);

    zero_acc_kernel<<<1, 32>>>();
    normalize_kernel<<<B_, 256>>>(V, Tx);
    colnorm_kernel<<<(CPAD + 255) / 256, 256>>>(W, Wt);
    transpose_convert_kernel<<<dim3(CPAD / 32, D_ / 32), dim3(32, 8)>>>(W, Wt);

    dim3 gnn(CPAD / 128, B_ / 128);
    gemm_hmma<<<gnn, 256, DSMEM>>>(vn16, W16t, logA, LSTRIDE);   // visual logits
    gemm_hmma<<<gnn, 256, DSMEM>>>(tn16, W16t, logB, LSTRIDE);   // textual logits
    vt_loss_kernel<<<B_, 256>>>(logA, logB, labels);
    gemm_hmma<<<gnn, 256, DSMEM>>>(tn16, Wt16t, logA, LSTRIDE);  // filter logits (reuse)
    ce_kernel<<<B_, 256>>>(logA, labels, 2);

    dim3 gnt(B_ / 128, B_ / 128);
    gemm_hmma<<<gnt, 256, DSMEM>>>(vn16, vn16, Gv, B_);
    gemm_hmma<<<gnt, 256, DSMEM>>>(tn16, tn16, Gt, B_);
    gemm_hmma<<<gnt, 256, DSMEM>>>(vn16, tn16, Gs, B_);
    hdr_kernel<<<B_, 256>>>();
    galign_kernel<<<2048, 256>>>(labels);

    finalize_kernel<<<1, 1>>>(out);
}

// round 7
// speedup vs baseline: 6.4545x; 1.1062x over previous
#include <cuda_runtime.h>
#include <cuda_bf16.h>
#include <stdint.h>
#include <math.h>
#include <float.h>

#define B_ 4096
#define D_ 1024
#define C_ 11003
#define CPAD 11008
#define LSTRIDE 11008
#define SCALE_ 28.0f
#define EPS_LS_ 0.1f
#define T_ 4.0f
#define SPOS_ 10.0f
#define SNEG_ 40.0f
#define ALPHA_ 0.6f
#define BETA_ 0.4f
#define HDR_A_ 3.0f
#define PLEN_ 63

typedef unsigned short ushortt;

// ---------------- scratch ----------------
__device__ ushortt g_vn16[(size_t)B_ * D_];
__device__ ushortt g_tn16[(size_t)B_ * D_];
__device__ ushortt g_W16t[(size_t)CPAD * D_];   // transposed, prescaled 28/colnorm
__device__ ushortt g_Wt16t[(size_t)CPAD * D_];
__device__ float g_invW[CPAD];
__device__ float g_invWt[CPAD];
__device__ float g_sqv[B_];
__device__ float g_sqt[B_];
__device__ float g_logA[(size_t)B_ * LSTRIDE];
__device__ float g_logB[(size_t)B_ * LSTRIDE];
__device__ float g_Gv[(size_t)B_ * B_];
__device__ float g_Gt[(size_t)B_ * B_];
__device__ float g_Gs[(size_t)B_ * B_];
// 0=CE_v 1=CE_t 2=CE_filter 3=dist_f 4=KL 5=HDR 6=GA
__device__ double g_acc[8];

__global__ void zero_acc_kernel() {
    if (threadIdx.x < 8) g_acc[threadIdx.x] = 0.0;
}

// ---------------- PTX helpers ----------------
__device__ __forceinline__ uint32_t smem_u32(const void* p) {
    return (uint32_t)__cvta_generic_to_shared((void*)p);
}
#define CP_ASYNC16(dst, src) \
    asm volatile("cp.async.cg.shared.global [%0], [%1], 16;\n" :: "r"(dst), "l"(src))
#define CP_COMMIT() asm volatile("cp.async.commit_group;\n" ::: "memory")
#define CP_WAIT(N) asm volatile("cp.async.wait_group %0;\n" :: "n"(N) : "memory")

#define LDSM4(d0, d1, d2, d3, a) \
    asm volatile("ldmatrix.sync.aligned.m8n8.x4.shared.b16 {%0,%1,%2,%3}, [%4];" \
                 : "=r"(d0), "=r"(d1), "=r"(d2), "=r"(d3) : "r"(a))

#define MMA_BF16(dd, aa, bb)                                                     \
    asm volatile(                                                                \
        "mma.sync.aligned.m16n8k16.row.col.f32.bf16.bf16.f32 "                   \
        "{%0,%1,%2,%3}, {%4,%5,%6,%7}, {%8,%9}, {%0,%1,%2,%3};\n"                \
        : "+f"(dd[0]), "+f"(dd[1]), "+f"(dd[2]), "+f"(dd[3])                     \
        : "r"(aa[0]), "r"(aa[1]), "r"(aa[2]), "r"(aa[3]), "r"(bb[0]), "r"(bb[1]))

#define SWZ(off) ((off) ^ (((off) >> 3) & 0x70))

// ---------------- HMMA GEMM: Out[M,N](ldOut) = A[M,K] @ B[N,K]^T, bf16 in fp32 out --------
// CTA tile 128(M)x256(N), BK=64, 8 warps as 2m x 4n (warp tile 64x64), 3-stage cp.async.
// k-step advance on swizzled addresses is XOR (bits 5-6 disjoint from bit-4 selector).
// Stage/row-block offsets are additive (+32 rows preserves row&7).
#define BKB 128                 // bytes per tile row (64 bf16)
#define A_STG 16384             // 128 rows * 128B
#define STG_BYTES 49152         // A(16K) + B(32K) per stage
#define NSTG 3

__global__ void __launch_bounds__(256, 1) gemm_hmma(
    const ushortt* __restrict__ A, const ushortt* __restrict__ Bsrc,
    float* __restrict__ Out, int ldOut) {
    extern __shared__ char sm[];
    const uint32_t smBase = smem_u32(sm);

    const int tid = threadIdx.x;
    const int lane = tid & 31, w = tid >> 5;
    const int wm = w & 1, wn = w >> 1;
    const int g = lane >> 2, tg = lane & 3;
    const int rowBase = blockIdx.y * 128, colBase = blockIdx.x * 256;

    // ---- cp.async mapping: thread covers row (tid>>3), chunk (tid&7); i steps +32 rows ----
    const int ldRow = tid >> 3, ldCh = tid & 7;
    const uint32_t stBase = SWZ((uint32_t)(ldRow * BKB + ldCh * 16));  // additive in +4096 steps
    const ushortt* srcA0 = A + (size_t)(rowBase + ldRow) * D_ + ldCh * 8;
    const ushortt* srcB0 = Bsrc + (size_t)(colBase + ldRow) * D_ + ldCh * 8;

    // ---- ldmatrix lane addresses (swizzled, k-step 0) ----
    uint32_t aAddr[4];
    {
        int grp = lane >> 3, r = lane & 7;
#pragma unroll
        for (int mt = 0; mt < 4; mt++) {
            int row = wm * 64 + mt * 16 + (grp & 1) * 8 + r;
            aAddr[mt] = SWZ((uint32_t)(row * BKB + (grp >> 1) * 16));
        }
    }
    uint32_t bAddr[4];
    {
        int grp = lane >> 3, r = lane & 7;
#pragma unroll
        for (int h = 0; h < 4; h++) {
            int row = wn * 64 + h * 16 + (grp >> 1) * 8 + r;
            bAddr[h] = SWZ((uint32_t)(row * BKB + (grp & 1) * 16)) + A_STG;
        }
    }

    float acc[4][8][4];
#pragma unroll
    for (int i = 0; i < 4; i++)
#pragma unroll
        for (int j = 0; j < 8; j++)
#pragma unroll
            for (int k = 0; k < 4; k++) acc[i][j][k] = 0.f;

    auto load_stage = [&](int kc, int stg) {
        const uint32_t base = smBase + stg * STG_BYTES;
        const int k0 = kc * 64;
#pragma unroll
        for (int i = 0; i < 4; i++)
            CP_ASYNC16(base + stBase + i * 4096u, srcA0 + (size_t)i * 32 * D_ + k0);
#pragma unroll
        for (int i = 0; i < 8; i++)
            CP_ASYNC16(base + A_STG + stBase + i * 4096u, srcB0 + (size_t)i * 32 * D_ + k0);
    };

    load_stage(0, 0); CP_COMMIT();
    load_stage(1, 1); CP_COMMIT();

#pragma unroll 1
    for (int c = 0; c < 16; c++) {
        const int stg = c % NSTG;
        if (c < 14) { CP_WAIT(1); } else { CP_WAIT(0); }
        __syncthreads();
        if (c + 2 < 16) { load_stage(c + 2, (c + 2) % NSTG); CP_COMMIT(); }

        const uint32_t base = smBase + stg * STG_BYTES;
#pragma unroll
        for (int ks = 0; ks < 4; ks++) {
            const uint32_t kx = ks * 32;   // XOR-step within the 128B swizzled row
            uint32_t a[4][4], b[8][2];
#pragma unroll
            for (int mt = 0; mt < 4; mt++)
                LDSM4(a[mt][0], a[mt][1], a[mt][2], a[mt][3], base + (aAddr[mt] ^ kx));
#pragma unroll
            for (int h = 0; h < 4; h++)
                LDSM4(b[2 * h][0], b[2 * h][1], b[2 * h + 1][0], b[2 * h + 1][1],
                      base + (bAddr[h] ^ kx));
#pragma unroll
            for (int mt = 0; mt < 4; mt++)
#pragma unroll
                for (int nt = 0; nt < 8; nt++) MMA_BF16(acc[mt][nt], a[mt], b[nt]);
        }
    }

    // ---- epilogue (Out padded wide enough; no guards) ----
#pragma unroll
    for (int mt = 0; mt < 4; mt++) {
        const int row = rowBase + wm * 64 + mt * 16 + g;
#pragma unroll
        for (int nt = 0; nt < 8; nt++) {
            const int col = colBase + wn * 64 + nt * 8 + tg * 2;
            float* o0 = Out + (size_t)row * ldOut + col;
            *(float2*)o0 = make_float2(acc[mt][nt][0], acc[mt][nt][1]);
            *(float2*)(o0 + (size_t)8 * ldOut) = make_float2(acc[mt][nt][2], acc[mt][nt][3]);
        }
    }
}

// ---------------- prep kernels ----------------
__global__ void normalize_kernel(const float* __restrict__ V, const float* __restrict__ Tm) {
    const int row = blockIdx.x;
    const int tid = threadIdx.x;
    const float* v = V + (size_t)row * D_;
    const float* t = Tm + (size_t)row * D_;

    float vv[4], tt[4];
    float lv = 0.f, lt = 0.f;
#pragma unroll
    for (int i = 0; i < 4; i++) {
        vv[i] = v[tid + 256 * i];
        tt[i] = t[tid + 256 * i];
        lv += vv[i] * vv[i];
        lt += tt[i] * tt[i];
    }
    __shared__ float s1[256], s2[256];
    s1[tid] = lv; s2[tid] = lt;
    __syncthreads();
    for (int s = 128; s > 0; s >>= 1) {
        if (tid < s) { s1[tid] += s1[tid + s]; s2[tid] += s2[tid + s]; }
        __syncthreads();
    }
    const float iv = 1.0f / sqrtf(s1[0]);
    const float it = 1.0f / sqrtf(s2[0]);
    __syncthreads();

    float ld = 0.f, qv = 0.f, qt = 0.f;
#pragma unroll
    for (int i = 0; i < 4; i++) {
        float a = vv[i] * iv;
        float b = tt[i] * it;
        __nv_bfloat16 ha = __float2bfloat16(a);
        __nv_bfloat16 hb = __float2bfloat16(b);
        g_vn16[(size_t)row * D_ + tid + 256 * i] = __bfloat16_as_ushort(ha);
        g_tn16[(size_t)row * D_ + tid + 256 * i] = __bfloat16_as_ushort(hb);
        float af = __bfloat162float(ha);
        float bf = __bfloat162float(hb);
        qv += af * af;
        qt += bf * bf;
        float df = a - b;
        ld += df * df;
    }
    s1[tid] = ld; s2[tid] = qv;
    __syncthreads();
    for (int s = 128; s > 0; s >>= 1) {
        if (tid < s) { s1[tid] += s1[tid + s]; s2[tid] += s2[tid + s]; }
        __syncthreads();
    }
    if (tid == 0) {
        atomicAdd(&g_acc[3], (double)s1[0]);
        g_sqv[row] = s2[0];
    }
    __syncthreads();
    s1[tid] = qt;
    __syncthreads();
    for (int s = 128; s > 0; s >>= 1) {
        if (tid < s) s1[tid] += s1[tid + s];
        __syncthreads();
    }
    if (tid == 0) g_sqt[row] = s1[0];
}

__global__ void colnorm_kernel(const float* __restrict__ W, const float* __restrict__ Wt) {
    const int c = blockIdx.x * blockDim.x + threadIdx.x;
    if (c >= CPAD) return;
    if (c < C_) {
        float s1 = 0.f, s2 = 0.f;
        for (int d = 0; d < D_; d++) {
            float a = W[(size_t)d * C_ + c];
            float b = Wt[(size_t)d * C_ + c];
            s1 += a * a;
            s2 += b * b;
        }
        g_invW[c] = SCALE_ / sqrtf(s1);
        g_invWt[c] = SCALE_ / sqrtf(s2);
    } else {
        g_invW[c] = 0.f;
        g_invWt[c] = 0.f;
    }
}

// 32x32 tile transpose W[d][c] -> W16t[c][d] (scaled, bf16), both matrices.
__global__ void transpose_convert_kernel(const float* __restrict__ W, const float* __restrict__ Wt) {
    __shared__ float t1[32][33];
    __shared__ float t2[32][33];
    const int c0 = blockIdx.x * 32, d0 = blockIdx.y * 32;
    const int tx = threadIdx.x, ty = threadIdx.y;
#pragma unroll
    for (int i = 0; i < 4; i++) {
        int d = d0 + ty + i * 8;
        int c = c0 + tx;
        float v1 = 0.f, v2 = 0.f;
        if (c < C_) {
            v1 = W[(size_t)d * C_ + c] * g_invW[c];
            v2 = Wt[(size_t)d * C_ + c] * g_invWt[c];
        }
        t1[ty + i * 8][tx] = v1;
        t2[ty + i * 8][tx] = v2;
    }
    __syncthreads();
#pragma unroll
    for (int i = 0; i < 4; i++) {
        int c = c0 + ty + i * 8;
        int d = d0 + tx;
        g_W16t[(size_t)c * D_ + d] = __bfloat16_as_ushort(__float2bfloat16(t1[tx][ty + i * 8]));
        g_Wt16t[(size_t)c * D_ + d] = __bfloat16_as_ushort(__float2bfloat16(t2[tx][ty + i * 8]));
    }
}

// ---------------- fused CE_v + CE_t + KL, single pass ----------------
__global__ void vt_loss_kernel(const float* __restrict__ logA, const float* __restrict__ logB,
                               const int* __restrict__ labels) {
    const int row = blockIdx.x;
    const int tid = threadIdx.x;
    const float* xA = logA + (size_t)row * LSTRIDE;
    const float* xB = logB + (size_t)row * LSTRIDE;

    float sA = 0.f, sxA = 0.f, sB = 0.f, sxB = 0.f, zT = 0.f, zS = 0.f, wd = 0.f;
    for (int c = tid; c < C_; c += 256) {
        float a = xA[c], b = xB[c];
        sA += __expf(a - SCALE_);
        sB += __expf(b - SCALE_);
        float ea = __expf(a * 0.25f - 7.f);
        float eb = __expf(b * 0.25f - 7.f);
        zT += ea; zS += eb;
        wd += ea * (a - b);
        sxA += a; sxB += b;
    }
    float vals[7] = {sA, sxA, sB, sxB, zT, zS, wd};
#pragma unroll
    for (int q = 0; q < 7; q++)
#pragma unroll
        for (int o = 16; o > 0; o >>= 1) vals[q] += __shfl_xor_sync(0xffffffffu, vals[q], o);
    __shared__ float red[8][7];
    if ((tid & 31) == 0)
#pragma unroll
        for (int q = 0; q < 7; q++) red[tid >> 5][q] = vals[q];
    __syncthreads();
    if (tid == 0) {
        double r[7];
        for (int q = 0; q < 7; q++) {
            double s = 0.0;
            for (int k = 0; k < 8; k++) s += (double)red[k][q];
            r[q] = s;
        }
        const int lab = labels[row];
        double lseA = (double)SCALE_ + log(r[0]);
        double lseB = (double)SCALE_ + log(r[2]);
        double ceA = -((1.0 - (double)EPS_LS_) * ((double)xA[lab] - lseA) +
                       ((double)EPS_LS_ / C_) * (r[1] - (double)C_ * lseA));
        double ceB = -((1.0 - (double)EPS_LS_) * ((double)xB[lab] - lseB) +
                       ((double)EPS_LS_ / C_) * (r[3] - (double)C_ * lseB));
        double kl = r[6] / ((double)T_ * r[4]) + log(r[5]) - log(r[4]);
        atomicAdd(&g_acc[0], ceA);
        atomicAdd(&g_acc[1], ceB);
        atomicAdd(&g_acc[4], kl);
    }
}

__global__ void ce_kernel(const float* __restrict__ logits, const int* __restrict__ labels,
                          int accIdx) {
    const int row = blockIdx.x;
    const int tid = threadIdx.x;
    const float* x = logits + (size_t)row * LSTRIDE;
    float se = 0.f, sx = 0.f;
    for (int c = tid; c < C_; c += 256) {
        float v = x[c];
        se += __expf(v - SCALE_);
        sx += v;
    }
#pragma unroll
    for (int o = 16; o > 0; o >>= 1) {
        se += __shfl_xor_sync(0xffffffffu, se, o);
        sx += __shfl_xor_sync(0xffffffffu, sx, o);
    }
    __shared__ float r1[8], r2[8];
    if ((tid & 31) == 0) { r1[tid >> 5] = se; r2[tid >> 5] = sx; }
    __syncthreads();
    if (tid == 0) {
        double s1 = 0.0, s2 = 0.0;
        for (int k = 0; k < 8; k++) { s1 += (double)r1[k]; s2 += (double)r2[k]; }
        double lse = (double)SCALE_ + log(s1);
        double ce = -((1.0 - (double)EPS_LS_) * ((double)x[labels[row]] - lse) +
                      ((double)EPS_LS_ / C_) * (s2 - (double)C_ * lse));
        atomicAdd(&g_acc[accIdx], ce);
    }
}

// ---------------- HardDarkRank (incremental argmax) ----------------
__global__ void hdr_kernel() {
    const int row = blockIdx.x;
    const int tid = threadIdx.x;
    __shared__ float score[B_];
    __shared__ float bv[256];
    __shared__ int bi[256];
    __shared__ int s_win;
    __shared__ int s_idxs[PLEN_];
    __shared__ float ord[PLEN_];

    const float sq_r = g_sqv[row];
    for (int j = tid; j < B_; j += 256) {
        float gg = g_Gv[(size_t)row * B_ + j];
        float d2 = fmaxf(sq_r + g_sqv[j] - 2.0f * gg, 1e-12f);
        float d = sqrtf(d2);
        score[j] = (j == row) ? -FLT_MAX : (-HDR_A_ * d * d * d);
    }
    __syncthreads();

    // per-thread running best over its strided 16 elements (strict > keeps smallest idx)
    {
        float v = -FLT_MAX; int ii = 0x7fffffff;
        for (int j = tid; j < B_; j += 256) {
            float s = score[j];
            if (s > v) { v = s; ii = j; }
        }
        bv[tid] = v; bi[tid] = ii;
    }
    __syncthreads();

#pragma unroll 1
    for (int k = 0; k < PLEN_; k++) {
        if (tid < 32) {
            float best = -FLT_MAX; int bidx = 0x7fffffff;
#pragma unroll
            for (int q = 0; q < 8; q++) {
                float v = bv[tid + q * 32]; int ii = bi[tid + q * 32];
                if (v > best || (v == best && ii < bidx)) { best = v; bidx = ii; }
            }
#pragma unroll
            for (int o = 16; o > 0; o >>= 1) {
                float ov = __shfl_down_sync(0xffffffffu, best, o);
                int oi = __shfl_down_sync(0xffffffffu, bidx, o);
                if (ov > best || (ov == best && oi < bidx)) { best = ov; bidx = oi; }
            }
            if (tid == 0) {
                s_win = bidx;
                s_idxs[k] = bidx;
                score[bidx] = -FLT_MAX;
            }
        }
        __syncthreads();
        const int winIdx = s_win;
        if ((winIdx & 255) == tid) {   // owner rescans its 16 elements
            float v = -FLT_MAX; int ii = 0x7fffffff;
            for (int j = tid; j < B_; j += 256) {
                float s = score[j];
                if (s > v) { v = s; ii = j; }
            }
            bv[tid] = v; bi[tid] = ii;
        }
        __syncthreads();
    }

    const float sqt_r = g_sqt[row];
    if (tid < PLEN_) {
        int j = s_idxs[tid];
        float gg = g_Gt[(size_t)row * B_ + j];
        float d2 = fmaxf(sqt_r + g_sqt[j] - 2.0f * gg, 1e-12f);
        float d = sqrtf(d2);
        ord[tid] = -HDR_A_ * d * d * d;
    }
    __syncthreads();
    if (tid == 0) {
        float acc = -FLT_MAX;
        float total = 0.f;
        for (int k = PLEN_ - 1; k >= 0; k--) {
            float o = ord[k];
            if (acc == -FLT_MAX) acc = o;
            else {
                float mx = fmaxf(acc, o);
                acc = mx + log1pf(__expf(fminf(acc, o) - mx));
            }
            total += o - acc;
        }
        atomicAdd(&g_acc[5], (double)(-total));
    }
}

// ---------------- global align ----------------
__global__ void galign_kernel(const int* __restrict__ labels) {
    const int tid = threadIdx.x;
    const size_t stride = (size_t)gridDim.x * blockDim.x;
    double local = 0.0;
    for (size_t e = (size_t)blockIdx.x * blockDim.x + tid; e < (size_t)B_ * B_; e += stride) {
        int i = (int)(e >> 12);
        int j = (int)(e & 4095);
        float sim = g_Gs[e];
        bool same = labels[i] == labels[j];
        float x = same ? (-SPOS_ * (sim - ALPHA_)) : (SNEG_ * (sim - BETA_));
        local += (double)log1pf(__expf(x));
    }
    __shared__ double sd[256];
    sd[tid] = local;
    __syncthreads();
    for (int s = 128; s > 0; s >>= 1) {
        if (tid < s) sd[tid] += sd[tid + s];
        __syncthreads();
    }
    if (tid == 0) atomicAdd(&g_acc[6], sd[0]);
}

__global__ void finalize_kernel(float* out) {
    const double invB = 1.0 / (double)B_;
    double v = (g_acc[0] + g_acc[1] + g_acc[2]) * invB
             + g_acc[3] * invB
             + g_acc[4] * invB
             + 0.1 * g_acc[5] * invB
             + 2.0 * g_acc[6] * invB;
    out[0] = (float)v;
}

// ---------------- launch ----------------
extern "C" void kernel_launch(void* const* d_in, const int* in_sizes, int n_in,
                              void* d_out, int out_size) {
    const float* V = (const float*)d_in[0];
    const float* Tx = (const float*)d_in[1];
    const int* labels = (const int*)d_in[2];
    const float* W = (const float*)d_in[3];
    const float* Wt = (const float*)d_in[4];
    float* out = (float*)d_out;

    ushortt *vn16, *tn16, *W16t, *Wt16t;
    float *logA, *logB, *Gv, *Gt, *Gs;
    cudaGetSymbolAddress((void**)&vn16, g_vn16);
    cudaGetSymbolAddress((void**)&tn16, g_tn16);
    cudaGetSymbolAddress((void**)&W16t, g_W16t);
    cudaGetSymbolAddress((void**)&Wt16t, g_Wt16t);
    cudaGetSymbolAddress((void**)&logA, g_logA);
    cudaGetSymbolAddress((void**)&logB, g_logB);
    cudaGetSymbolAddress((void**)&Gv, g_Gv);
    cudaGetSymbolAddress((void**)&Gt, g_Gt);
    cudaGetSymbolAddress((void**)&Gs, g_Gs);

    const int DSMEM = NSTG * STG_BYTES;   // 147456
    cudaFuncSetAttribute(gemm_hmma, cudaFuncAttributeMaxDynamicSharedMemorySize, DSMEM);

    zero_acc_kernel<<<1, 32>>>();
    normalize_kernel<<<B_, 256>>>(V, Tx);
    colnorm_kernel<<<(CPAD + 255) / 256, 256>>>(W, Wt);
    transpose_convert_kernel<<<dim3(CPAD / 32, D_ / 32), dim3(32, 8)>>>(W, Wt);

    dim3 gnn(CPAD / 256, B_ / 128);
    gemm_hmma<<<gnn, 256, DSMEM>>>(vn16, W16t, logA, LSTRIDE);   // visual logits
    gemm_hmma<<<gnn, 256, DSMEM>>>(tn16, W16t, logB, LSTRIDE);   // textual logits
    vt_loss_kernel<<<B_, 256>>>(logA, logB, labels);
    gemm_hmma<<<gnn, 256, DSMEM>>>(tn16, Wt16t, logA, LSTRIDE);  // filter logits (reuse)
    ce_kernel<<<B_, 256>>>(logA, labels, 2);

    dim3 gnt(B_ / 256, B_ / 128);
    gemm_hmma<<<gnt, 256, DSMEM>>>(vn16, vn16, Gv, B_);
    gemm_hmma<<<gnt, 256, DSMEM>>>(tn16, tn16, Gt, B_);
    gemm_hmma<<<gnt, 256, DSMEM>>>(vn16, tn16, Gs, B_);
    hdr_kernel<<<B_, 256>>>();
    galign_kernel<<<2048, 256>>>(labels);

    finalize_kernel<<<1, 1>>>(out);
}